// round 13
// baseline (speedup 1.0000x reference)
#include <cuda_runtime.h>
#include <cuda_fp16.h>
#include <cstdint>
#include <math.h>

// ---------------- problem constants ----------------
#define NPTS 100000
#define KNBR 9
#define CDIM 256
#define BM   64                   // rows per CTA
#define THREADS 256               // 8 warps: 2 (M) x 4 (N), warp tile 32x64
#define NKT  36                   // 9 neighbors * 256/64
#define NSTG 2                    // cp.async pipeline depth
#define RS   72                   // smem row stride in halves (64 + 8 pad = 144B)
#define A_STG_B (BM * RS * 2)     // 9216
#define B_STG_B (CDIM * RS * 2)   // 36864

// ---------------- scratch ----------------
__device__ int    g_nbr[NPTS * KNBR];
__device__ __half g_hfeats[(size_t)NPTS * CDIM];
__device__ __half g_mid[(size_t)NPTS * CDIM];
__device__ __half g_WT1[KNBR * CDIM * CDIM];   // [kk][d][c] (n-major), fp16
__device__ __half g_WT2[KNBR * CDIM * CDIM];

// ---------------- smem ----------------
struct Smem {
    __half As[NSTG][BM][RS];      // 18432 B
    __half Bs[NSTG][CDIM][RS];    // 73728 B
    int    nbr[BM * KNBR];        //  2304 B
    float  gam[CDIM], bet[CDIM];  //  2048 B
    float  red1[BM][4], red2[BM][4];
    float  mu[BM], inv[BM];
};                                 // ~99 KB

// ---------------- helpers ----------------
__device__ __forceinline__ void cp16(uint32_t dst, const void* src, uint32_t sz) {
    asm volatile("cp.async.cg.shared.global [%0], [%1], 16, %2;"
                 :: "r"(dst), "l"(src), "r"(sz) : "memory");
}
#define CP_COMMIT() asm volatile("cp.async.commit_group;" ::: "memory")
#define CP_WAIT0()  asm volatile("cp.async.wait_group 0;" ::: "memory")

__device__ __forceinline__ void ldsm4(uint32_t* r, uint32_t addr) {
    asm volatile("ldmatrix.sync.aligned.m8n8.x4.shared.b16 {%0,%1,%2,%3}, [%4];"
                 : "=r"(r[0]), "=r"(r[1]), "=r"(r[2]), "=r"(r[3]) : "r"(addr));
}
// fp16-accumulate MMA: D(f16x4 in 2 regs) = A*B + D. Same (row,col) frag
// mapping as the f32 variant: reg0 = {c0,c1}, reg1 = {c2,c3}.
__device__ __forceinline__ void mma16h(uint32_t* c, const uint32_t* a, uint32_t b0, uint32_t b1) {
    asm volatile(
        "mma.sync.aligned.m16n8k16.row.col.f16.f16.f16.f16 "
        "{%0,%1}, {%2,%3,%4,%5}, {%6,%7}, {%0,%1};"
        : "+r"(c[0]), "+r"(c[1])
        : "r"(a[0]), "r"(a[1]), "r"(a[2]), "r"(a[3]), "r"(b0), "r"(b1));
}
__device__ __forceinline__ float gelu_exact(float x) {
    return 0.5f * x * (1.0f + erff(x * 0.70710678118654752f));
}

// ---------------- pre-pass kernels ----------------
__global__ void build_nbr_kernel(const int* __restrict__ idx, const void* __restrict__ mask) {
    __shared__ int flag;
    if (threadIdx.x == 0) flag = 0;
    __syncthreads();
    const unsigned int* mw = (const unsigned int*)mask;
    for (int i = threadIdx.x; i < 1024; i += blockDim.x) {
        unsigned w = mw[i];
        if (w != 0u && w != 1u && w != 0x3F800000u) flag = 1;  // u8-packed pattern
    }
    __syncthreads();
    const bool u8 = (flag != 0);
    int i = blockIdx.x * blockDim.x + threadIdx.x;
    if (i >= NPTS * KNBR) return;
    bool on = u8 ? (((const unsigned char*)mask)[i] != 0)
                 : (((const unsigned int*)mask)[i] != 0u);
    g_nbr[i] = on ? idx[i] : -1;
}

__global__ void f2h_kernel(const float* __restrict__ in, __half* __restrict__ out) {
    const int n4 = NPTS * CDIM / 4;
    for (int i = blockIdx.x * blockDim.x + threadIdx.x; i < n4; i += gridDim.x * blockDim.x) {
        float4 v = __ldg((const float4*)in + i);
        __half2 h0 = __floats2half2_rn(v.x, v.y);
        __half2 h1 = __floats2half2_rn(v.z, v.w);
        ((uint2*)out)[i] = make_uint2(*(uint32_t*)&h0, *(uint32_t*)&h1);
    }
}

__global__ void transpose_w2(const float* __restrict__ W1, const float* __restrict__ W2,
                             __half* __restrict__ WT1, __half* __restrict__ WT2) {
    __shared__ float t[32][33];
    const int z = blockIdx.z;
    const int kk = (z >= KNBR) ? z - KNBR : z;
    const float* Wk = ((z >= KNBR) ? W2 : W1) + (size_t)kk * 65536;
    __half* Tk = ((z >= KNBR) ? WT2 : WT1) + (size_t)kk * 65536;
    int c0 = blockIdx.x * 32, d0 = blockIdx.y * 32;
    int x = threadIdx.x, y = threadIdx.y;
#pragma unroll
    for (int j = 0; j < 32; j += 8) t[y + j][x] = Wk[(c0 + y + j) * 256 + d0 + x];
    __syncthreads();
#pragma unroll
    for (int j = 0; j < 32; j += 8) Tk[(d0 + y + j) * 256 + c0 + x] = __float2half(t[x][y + j]);
}

// ---------------- stage loader (cp.async, 64-channel chunk, 256 thr) ----------------
__device__ __forceinline__ void issue_stage(Smem* sm, int st, int kt,
                                            const __half* __restrict__ src,
                                            const __half* __restrict__ WT, int tid) {
    const int kk = kt >> 2;            // neighbor slot
    const int cb = (kt & 3) << 6;      // channel base (halves)
    // A gather: 64 rows x 64 halves (128B/row); 4 threads/row, 2 x 16B each
    {
        const int row = tid >> 2, j = tid & 3;
        const int r = sm->nbr[row * KNBR + kk];
        const uint32_t sz = (r >= 0) ? 16u : 0u;
        const __half* gp = src + ((size_t)(r >= 0 ? r : 0) << 8) + cb;
        cp16((uint32_t)__cvta_generic_to_shared(&sm->As[st][row][j * 8]),      gp + j * 8,      sz);
        cp16((uint32_t)__cvta_generic_to_shared(&sm->As[st][row][j * 8 + 32]), gp + j * 8 + 32, sz);
    }
    // B: 256 n-rows x 64 halves; 8 x 16B per thread
    {
        const __half* wb = WT + ((size_t)kk << 16) + cb;
#pragma unroll
        for (int q = 0; q < 8; q++) {
            const int c = q * THREADS + tid;
            const int n = c >> 3, kq = c & 7;
            cp16((uint32_t)__cvta_generic_to_shared(&sm->Bs[st][n][kq * 8]),
                 wb + ((size_t)n << 8) + kq * 8, 16u);
        }
    }
}

// ---------------- fused fp16 mma conv + LN + GELU (+res) ----------------
// f16 accumulate within each 64-channel chunk, promote to f32 per chunk.
template <bool HAS_RES, bool HALF_OUT>
__global__ __launch_bounds__(THREADS, 1)
void conv_mma(const __half* __restrict__ src, const __half* __restrict__ WT,
              const float* __restrict__ gamma, const float* __restrict__ beta,
              const float* __restrict__ resid, void* __restrict__ dst_v) {
    extern __shared__ unsigned char sm_raw[];
    Smem* sm = (Smem*)sm_raw;

    const int tid  = threadIdx.x;
    const int lane = tid & 31;
    const int wid  = tid >> 5;
    const int wm   = wid >> 2;  // 0..1: rows wm*32..+32
    const int wn   = wid & 3;   // 0..3: cols wn*64..+64
    const int m0   = blockIdx.x * BM;

    for (int i = tid; i < BM * KNBR; i += THREADS) {
        int m = m0 + i / KNBR;
        sm->nbr[i] = (m < NPTS) ? g_nbr[(size_t)m * KNBR + (i % KNBR)] : -1;
    }
    if (tid < CDIM) { sm->gam[tid] = gamma[tid]; sm->bet[tid] = beta[tid]; }
    __syncthreads();

    // ---- ldmatrix lane addresses ----
    uint32_t aAddr[2];
    {
        const int rowsel = ((lane >> 3) & 1) * 8 + (lane & 7);
        const int kboff  = (lane >> 4) * 16;
#pragma unroll
        for (int mt = 0; mt < 2; mt++) {
            const int arow = wm * 32 + mt * 16 + rowsel;
            aAddr[mt] = (uint32_t)__cvta_generic_to_shared(&sm->As[0][0][0])
                        + (uint32_t)(arow * (RS * 2) + kboff);
        }
    }
    uint32_t bAddr[4];
    {
        const int nrowsel = ((lane >> 4) & 1) * 8 + (lane & 7);
        const int kboff   = ((lane >> 3) & 1) * 16;
#pragma unroll
        for (int p = 0; p < 4; p++) {
            const int brow = wn * 64 + p * 16 + nrowsel;
            bAddr[p] = (uint32_t)__cvta_generic_to_shared(&sm->Bs[0][0][0])
                       + (uint32_t)(brow * (RS * 2) + kboff);
        }
    }

    // prologue: stage 0
    issue_stage(sm, 0, 0, src, WT, tid);
    CP_COMMIT();

    float acc[2][8][4];            // fp32 master
#pragma unroll
    for (int mt = 0; mt < 2; mt++)
#pragma unroll
        for (int nt = 0; nt < 8; nt++)
#pragma unroll
            for (int e = 0; e < 4; e++) acc[mt][nt][e] = 0.0f;

    uint32_t facc[2][8][2];        // fp16 chunk accumulators (half2 x2)
#pragma unroll
    for (int mt = 0; mt < 2; mt++)
#pragma unroll
        for (int nt = 0; nt < 8; nt++) { facc[mt][nt][0] = 0u; facc[mt][nt][1] = 0u; }

    int cur = 0;
    for (int kt = 0; kt < NKT; ++kt) {
        CP_WAIT0();
        __syncthreads();

        if (kt + 1 < NKT)
            issue_stage(sm, cur ^ 1, kt + 1, src, WT, tid);
        CP_COMMIT();

        const uint32_t ao = (uint32_t)cur * A_STG_B;
        const uint32_t bo = (uint32_t)cur * B_STG_B;
#pragma unroll
        for (int ks = 0; ks < 4; ks++) {
            uint32_t af0[4], af1[4];
            ldsm4(af0, aAddr[0] + ao + ks * 32);
            ldsm4(af1, aAddr[1] + ao + ks * 32);
#pragma unroll
            for (int p = 0; p < 4; p++) {
                uint32_t bf[4];
                ldsm4(bf, bAddr[p] + bo + ks * 32);
                mma16h(facc[0][2 * p],     af0, bf[0], bf[1]);
                mma16h(facc[1][2 * p],     af1, bf[0], bf[1]);
                mma16h(facc[0][2 * p + 1], af0, bf[2], bf[3]);
                mma16h(facc[1][2 * p + 1], af1, bf[2], bf[3]);
            }
        }
        // ---- promote fp16 chunk sums into fp32 master, reset fp16 ----
#pragma unroll
        for (int mt = 0; mt < 2; mt++)
#pragma unroll
            for (int nt = 0; nt < 8; nt++) {
                __half2 h0 = *(__half2*)&facc[mt][nt][0];
                __half2 h1 = *(__half2*)&facc[mt][nt][1];
                float2 f0 = __half22float2(h0);
                float2 f1 = __half22float2(h1);
                acc[mt][nt][0] += f0.x; acc[mt][nt][1] += f0.y;
                acc[mt][nt][2] += f1.x; acc[mt][nt][3] += f1.y;
                facc[mt][nt][0] = 0u;   facc[mt][nt][1] = 0u;
            }
        cur ^= 1;
    }

    // ---- LayerNorm reduction ----
    __syncthreads();
#pragma unroll
    for (int mt = 0; mt < 2; mt++) {
        float s1a = 0.f, s2a = 0.f, s1b = 0.f, s2b = 0.f;
#pragma unroll
        for (int nt = 0; nt < 8; nt++) {
            float v0 = acc[mt][nt][0], v1 = acc[mt][nt][1];
            float v2 = acc[mt][nt][2], v3 = acc[mt][nt][3];
            s1a += v0 + v1; s2a += v0 * v0 + v1 * v1;
            s1b += v2 + v3; s2b += v2 * v2 + v3 * v3;
        }
#pragma unroll
        for (int o = 1; o < 4; o <<= 1) {
            s1a += __shfl_xor_sync(0xFFFFFFFFu, s1a, o);
            s2a += __shfl_xor_sync(0xFFFFFFFFu, s2a, o);
            s1b += __shfl_xor_sync(0xFFFFFFFFu, s1b, o);
            s2b += __shfl_xor_sync(0xFFFFFFFFu, s2b, o);
        }
        if ((lane & 3) == 0) {
            int r = (wm << 5) + (mt << 4) + (lane >> 2);
            sm->red1[r][wn] = s1a; sm->red2[r][wn] = s2a;
            sm->red1[r + 8][wn] = s1b; sm->red2[r + 8][wn] = s2b;
        }
    }
    __syncthreads();
    if (tid < BM) {
        float s1 = sm->red1[tid][0] + sm->red1[tid][1] + sm->red1[tid][2] + sm->red1[tid][3];
        float s2 = sm->red2[tid][0] + sm->red2[tid][1] + sm->red2[tid][2] + sm->red2[tid][3];
        float mu  = s1 * (1.0f / 256.0f);
        float var = s2 * (1.0f / 256.0f) - mu * mu;
        sm->mu[tid]  = mu;
        sm->inv[tid] = rsqrtf(var + 1e-6f);
    }
    __syncthreads();

    // ---- normalize + residual + GELU + store ----
#pragma unroll
    for (int mt = 0; mt < 2; mt++) {
#pragma unroll
        for (int hf = 0; hf < 2; hf++) {
            int r = (wm << 5) + (mt << 4) + (lane >> 2) + hf * 8;
            int m = m0 + r;
            if (m < NPTS) {
                float mu = sm->mu[r], inv = sm->inv[r];
#pragma unroll
                for (int nt = 0; nt < 8; nt++) {
                    int n = (wn << 6) + nt * 8 + ((lane & 3) << 1);
                    float v0 = acc[mt][nt][hf * 2 + 0];
                    float v1 = acc[mt][nt][hf * 2 + 1];
                    v0 = (v0 - mu) * inv * sm->gam[n]     + sm->bet[n];
                    v1 = (v1 - mu) * inv * sm->gam[n + 1] + sm->bet[n + 1];
                    if (HAS_RES) {
                        float2 rr = *(const float2*)(resid + (size_t)m * CDIM + n);
                        v0 += rr.x; v1 += rr.y;
                    }
                    v0 = gelu_exact(v0);
                    v1 = gelu_exact(v1);
                    if (HALF_OUT) {
                        __half2 h = __floats2half2_rn(v0, v1);
                        *(__half2*)((__half*)dst_v + (size_t)m * CDIM + n) = h;
                    } else {
                        *(float2*)((float*)dst_v + (size_t)m * CDIM + n) = make_float2(v0, v1);
                    }
                }
            }
        }
    }
}

// ---------------- launch (5 kernels) ----------------
extern "C" void kernel_launch(void* const* d_in, const int* in_sizes, int n_in,
                              void* d_out, int out_size) {
    const float* feats  = (const float*)d_in[0];
    const float* W1     = (const float*)d_in[1];
    const float* gamma1 = (const float*)d_in[2];
    const float* beta1  = (const float*)d_in[3];
    const float* W2     = (const float*)d_in[4];
    const float* gamma2 = (const float*)d_in[5];
    const float* beta2  = (const float*)d_in[6];
    const int*   nbr    = (const int*)d_in[7];
    const void*  mask   = (const void*)d_in[8];

    __half *hfeats, *mid, *wt1, *wt2;
    cudaGetSymbolAddress((void**)&hfeats, g_hfeats);
    cudaGetSymbolAddress((void**)&mid, g_mid);
    cudaGetSymbolAddress((void**)&wt1, g_WT1);
    cudaGetSymbolAddress((void**)&wt2, g_WT2);

    const int smem_bytes = (int)sizeof(Smem);
    cudaFuncSetAttribute(conv_mma<false, true>, cudaFuncAttributeMaxDynamicSharedMemorySize, smem_bytes);
    cudaFuncSetAttribute(conv_mma<true, false>, cudaFuncAttributeMaxDynamicSharedMemorySize, smem_bytes);

    dim3 tb(32, 8), tg(8, 8, 2 * KNBR);
    transpose_w2<<<tg, tb>>>(W1, W2, wt1, wt2);
    build_nbr_kernel<<<(NPTS * KNBR + 255) / 256, 256>>>(nbr, mask);
    f2h_kernel<<<1024, 256>>>(feats, hfeats);

    const int grid = (NPTS + BM - 1) / BM;  // 1563
    conv_mma<false, true><<<grid, THREADS, smem_bytes>>>(hfeats, wt1, gamma1, beta1, nullptr, mid);
    conv_mma<true, false><<<grid, THREADS, smem_bytes>>>(mid,  wt2, gamma2, beta2, feats, d_out);
}

// round 14
// speedup vs baseline: 1.4892x; 1.4892x over previous
#include <cuda_runtime.h>
#include <cuda_fp16.h>
#include <cstdint>
#include <math.h>

// ---------------- problem constants ----------------
#define NPTS 100000
#define KNBR 9
#define CDIM 256
#define BM   64                   // rows per CTA
#define THREADS 256               // 8 warps: 2 (M) x 4 (N), warp tile 32x64
#define NKT  36                   // 9 neighbors * 256/64
#define NSTG 2                    // cp.async pipeline depth
#define RS   72                   // smem row stride in halves (64 + 8 pad = 144B)
#define A_STG_B (BM * RS * 2)     // 9216
#define B_STG_B (CDIM * RS * 2)   // 36864

// fused pre-pass block ranges
#define TR_BLOCKS  1152           // 8 x 8 x 18 transpose tiles
#define NBR_BLOCKS 3516           // ceil(900000/256)
#define F2H_BLOCKS 512
#define PRE_BLOCKS (TR_BLOCKS + NBR_BLOCKS + F2H_BLOCKS)

// ---------------- scratch ----------------
__device__ int    g_nbr[NPTS * KNBR];
__device__ __half g_hfeats[(size_t)NPTS * CDIM];
__device__ __half g_mid[(size_t)NPTS * CDIM];
__device__ __half g_WT1[KNBR * CDIM * CDIM];   // [kk][d][c] (n-major), fp16
__device__ __half g_WT2[KNBR * CDIM * CDIM];

// ---------------- smem (conv) ----------------
struct Smem {
    __half As[NSTG][BM][RS];      // 18432 B
    __half Bs[NSTG][CDIM][RS];    // 73728 B
    int    nbr[BM * KNBR];        //  2304 B
    float  gam[CDIM], bet[CDIM];  //  2048 B
    float  red1[BM][4], red2[BM][4];
    float  mu[BM], inv[BM];
};                                 // ~99 KB -> 2 CTAs/SM

// ---------------- helpers ----------------
__device__ __forceinline__ void cp16(uint32_t dst, const void* src, uint32_t sz) {
    asm volatile("cp.async.cg.shared.global [%0], [%1], 16, %2;"
                 :: "r"(dst), "l"(src), "r"(sz) : "memory");
}
#define CP_COMMIT() asm volatile("cp.async.commit_group;" ::: "memory")
#define CP_WAIT0()  asm volatile("cp.async.wait_group 0;" ::: "memory")

__device__ __forceinline__ void ldsm4(uint32_t* r, uint32_t addr) {
    asm volatile("ldmatrix.sync.aligned.m8n8.x4.shared.b16 {%0,%1,%2,%3}, [%4];"
                 : "=r"(r[0]), "=r"(r[1]), "=r"(r[2]), "=r"(r[3]) : "r"(addr));
}
__device__ __forceinline__ void mma16(float* c, const uint32_t* a, uint32_t b0, uint32_t b1) {
    asm volatile(
        "mma.sync.aligned.m16n8k16.row.col.f32.f16.f16.f32 "
        "{%0,%1,%2,%3}, {%4,%5,%6,%7}, {%8,%9}, {%0,%1,%2,%3};"
        : "+f"(c[0]), "+f"(c[1]), "+f"(c[2]), "+f"(c[3])
        : "r"(a[0]), "r"(a[1]), "r"(a[2]), "r"(a[3]), "r"(b0), "r"(b1));
}
__device__ __forceinline__ float gelu_exact(float x) {
    return 0.5f * x * (1.0f + erff(x * 0.70710678118654752f));
}

// ---------------- fused pre-pass: transpose(W1,W2) + build_nbr + f2h ----------------
__global__ void prepass_kernel(const float* __restrict__ feats,
                               const float* __restrict__ W1,
                               const float* __restrict__ W2,
                               const int*   __restrict__ idx,
                               const void*  __restrict__ mask,
                               __half* __restrict__ hfeats,
                               __half* __restrict__ wt1,
                               __half* __restrict__ wt2) {
    const int b = blockIdx.x;
    const int tid = threadIdx.x;

    if (b < TR_BLOCKS) {
        // ---- weight transpose: WT[kk][d][c] = (half)W[kk][c][d] ----
        __shared__ float t[32][33];
        const int z   = b >> 6;          // 0..17
        const int rem = b & 63;
        const int c0  = (rem & 7) << 5;
        const int d0  = (rem >> 3) << 5;
        const int kk  = (z >= KNBR) ? z - KNBR : z;
        const float* Wk = ((z >= KNBR) ? W2 : W1) + (size_t)kk * 65536;
        __half* Tk = ((z >= KNBR) ? wt2 : wt1) + (size_t)kk * 65536;
        const int x = tid & 31, y = tid >> 5;   // y in 0..7
#pragma unroll
        for (int j = 0; j < 32; j += 8) t[y + j][x] = Wk[(c0 + y + j) * 256 + d0 + x];
        __syncthreads();
#pragma unroll
        for (int j = 0; j < 32; j += 8) Tk[(d0 + y + j) * 256 + c0 + x] = __float2half(t[x][y + j]);
    } else if (b < TR_BLOCKS + NBR_BLOCKS) {
        // ---- neighbor table with in-block mask-width detection ----
        __shared__ int flag;
        if (tid == 0) flag = 0;
        __syncthreads();
        const unsigned int* mw = (const unsigned int*)mask;
        for (int i = tid; i < 1024; i += THREADS) {
            unsigned w = mw[i];
            if (w != 0u && w != 1u && w != 0x3F800000u) flag = 1;  // u8-packed pattern
        }
        __syncthreads();
        const bool u8 = (flag != 0);
        const int i = (b - TR_BLOCKS) * THREADS + tid;
        if (i < NPTS * KNBR) {
            bool on = u8 ? (((const unsigned char*)mask)[i] != 0)
                         : (((const unsigned int*)mask)[i] != 0u);
            g_nbr[i] = on ? idx[i] : -1;
        }
    } else {
        // ---- feats f32 -> f16 (grid-stride over F2H_BLOCKS) ----
        const int bb = b - TR_BLOCKS - NBR_BLOCKS;
        const int n4 = NPTS * CDIM / 4;
        for (int i = bb * THREADS + tid; i < n4; i += F2H_BLOCKS * THREADS) {
            float4 v = __ldg((const float4*)feats + i);
            __half2 h0 = __floats2half2_rn(v.x, v.y);
            __half2 h1 = __floats2half2_rn(v.z, v.w);
            ((uint2*)hfeats)[i] = make_uint2(*(uint32_t*)&h0, *(uint32_t*)&h1);
        }
    }
}

// ---------------- stage loader (cp.async, 64-channel chunk, 256 thr) ----------------
__device__ __forceinline__ void issue_stage(Smem* sm, int st, int kt,
                                            const __half* __restrict__ src,
                                            const __half* __restrict__ WT, int tid) {
    const int kk = kt >> 2;            // neighbor slot
    const int cb = (kt & 3) << 6;      // channel base (halves)
    // A gather: 64 rows x 64 halves (128B/row); 4 threads/row, 2 x 16B each
    {
        const int row = tid >> 2, j = tid & 3;
        const int r = sm->nbr[row * KNBR + kk];
        const uint32_t sz = (r >= 0) ? 16u : 0u;
        const __half* gp = src + ((size_t)(r >= 0 ? r : 0) << 8) + cb;
        cp16((uint32_t)__cvta_generic_to_shared(&sm->As[st][row][j * 8]),      gp + j * 8,      sz);
        cp16((uint32_t)__cvta_generic_to_shared(&sm->As[st][row][j * 8 + 32]), gp + j * 8 + 32, sz);
    }
    // B: 256 n-rows x 64 halves; 8 x 16B per thread
    {
        const __half* wb = WT + ((size_t)kk << 16) + cb;
#pragma unroll
        for (int q = 0; q < 8; q++) {
            const int c = q * THREADS + tid;
            const int n = c >> 3, kq = c & 7;
            cp16((uint32_t)__cvta_generic_to_shared(&sm->Bs[st][n][kq * 8]),
                 wb + ((size_t)n << 8) + kq * 8, 16u);
        }
    }
}

// ---------------- fused fp16 mma conv + LN + GELU (+res) — R11-identical ----------------
template <bool HAS_RES, bool HALF_OUT>
__global__ __launch_bounds__(THREADS, 2)
void conv_mma(const __half* __restrict__ src, const __half* __restrict__ WT,
              const float* __restrict__ gamma, const float* __restrict__ beta,
              const float* __restrict__ resid, void* __restrict__ dst_v) {
    extern __shared__ unsigned char sm_raw[];
    Smem* sm = (Smem*)sm_raw;

    const int tid  = threadIdx.x;
    const int lane = tid & 31;
    const int wid  = tid >> 5;
    const int wm   = wid >> 2;  // 0..1: rows wm*32..+32
    const int wn   = wid & 3;   // 0..3: cols wn*64..+64
    const int m0   = blockIdx.x * BM;

    for (int i = tid; i < BM * KNBR; i += THREADS) {
        int m = m0 + i / KNBR;
        sm->nbr[i] = (m < NPTS) ? g_nbr[(size_t)m * KNBR + (i % KNBR)] : -1;
    }
    if (tid < CDIM) { sm->gam[tid] = gamma[tid]; sm->bet[tid] = beta[tid]; }
    __syncthreads();

    // ---- ldmatrix lane addresses ----
    uint32_t aAddr[2];
    {
        const int rowsel = ((lane >> 3) & 1) * 8 + (lane & 7);
        const int kboff  = (lane >> 4) * 16;
#pragma unroll
        for (int mt = 0; mt < 2; mt++) {
            const int arow = wm * 32 + mt * 16 + rowsel;
            aAddr[mt] = (uint32_t)__cvta_generic_to_shared(&sm->As[0][0][0])
                        + (uint32_t)(arow * (RS * 2) + kboff);
        }
    }
    uint32_t bAddr[4];
    {
        const int nrowsel = ((lane >> 4) & 1) * 8 + (lane & 7);
        const int kboff   = ((lane >> 3) & 1) * 16;
#pragma unroll
        for (int p = 0; p < 4; p++) {
            const int brow = wn * 64 + p * 16 + nrowsel;
            bAddr[p] = (uint32_t)__cvta_generic_to_shared(&sm->Bs[0][0][0])
                       + (uint32_t)(brow * (RS * 2) + kboff);
        }
    }

    // prologue: stage 0
    issue_stage(sm, 0, 0, src, WT, tid);
    CP_COMMIT();

    float acc[2][8][4];
#pragma unroll
    for (int mt = 0; mt < 2; mt++)
#pragma unroll
        for (int nt = 0; nt < 8; nt++)
#pragma unroll
            for (int e = 0; e < 4; e++) acc[mt][nt][e] = 0.0f;

    int cur = 0;
    for (int kt = 0; kt < NKT; ++kt) {
        CP_WAIT0();
        __syncthreads();

        if (kt + 1 < NKT)
            issue_stage(sm, cur ^ 1, kt + 1, src, WT, tid);
        CP_COMMIT();

        const uint32_t ao = (uint32_t)cur * A_STG_B;
        const uint32_t bo = (uint32_t)cur * B_STG_B;
#pragma unroll
        for (int ks = 0; ks < 4; ks++) {
            uint32_t af0[4], af1[4];
            ldsm4(af0, aAddr[0] + ao + ks * 32);
            ldsm4(af1, aAddr[1] + ao + ks * 32);
#pragma unroll
            for (int p = 0; p < 4; p++) {
                uint32_t bf[4];
                ldsm4(bf, bAddr[p] + bo + ks * 32);
                mma16(acc[0][2 * p],     af0, bf[0], bf[1]);
                mma16(acc[1][2 * p],     af1, bf[0], bf[1]);
                mma16(acc[0][2 * p + 1], af0, bf[2], bf[3]);
                mma16(acc[1][2 * p + 1], af1, bf[2], bf[3]);
            }
        }
        cur ^= 1;
    }

    // ---- LayerNorm reduction ----
    __syncthreads();
#pragma unroll
    for (int mt = 0; mt < 2; mt++) {
        float s1a = 0.f, s2a = 0.f, s1b = 0.f, s2b = 0.f;
#pragma unroll
        for (int nt = 0; nt < 8; nt++) {
            float v0 = acc[mt][nt][0], v1 = acc[mt][nt][1];
            float v2 = acc[mt][nt][2], v3 = acc[mt][nt][3];
            s1a += v0 + v1; s2a += v0 * v0 + v1 * v1;
            s1b += v2 + v3; s2b += v2 * v2 + v3 * v3;
        }
#pragma unroll
        for (int o = 1; o < 4; o <<= 1) {
            s1a += __shfl_xor_sync(0xFFFFFFFFu, s1a, o);
            s2a += __shfl_xor_sync(0xFFFFFFFFu, s2a, o);
            s1b += __shfl_xor_sync(0xFFFFFFFFu, s1b, o);
            s2b += __shfl_xor_sync(0xFFFFFFFFu, s2b, o);
        }
        if ((lane & 3) == 0) {
            int r = (wm << 5) + (mt << 4) + (lane >> 2);
            sm->red1[r][wn] = s1a; sm->red2[r][wn] = s2a;
            sm->red1[r + 8][wn] = s1b; sm->red2[r + 8][wn] = s2b;
        }
    }
    __syncthreads();
    if (tid < BM) {
        float s1 = sm->red1[tid][0] + sm->red1[tid][1] + sm->red1[tid][2] + sm->red1[tid][3];
        float s2 = sm->red2[tid][0] + sm->red2[tid][1] + sm->red2[tid][2] + sm->red2[tid][3];
        float mu  = s1 * (1.0f / 256.0f);
        float var = s2 * (1.0f / 256.0f) - mu * mu;
        sm->mu[tid]  = mu;
        sm->inv[tid] = rsqrtf(var + 1e-6f);
    }
    __syncthreads();

    // ---- normalize + residual + GELU + store ----
#pragma unroll
    for (int mt = 0; mt < 2; mt++) {
#pragma unroll
        for (int hf = 0; hf < 2; hf++) {
            int r = (wm << 5) + (mt << 4) + (lane >> 2) + hf * 8;
            int m = m0 + r;
            if (m < NPTS) {
                float mu = sm->mu[r], inv = sm->inv[r];
#pragma unroll
                for (int nt = 0; nt < 8; nt++) {
                    int n = (wn << 6) + nt * 8 + ((lane & 3) << 1);
                    float v0 = acc[mt][nt][hf * 2 + 0];
                    float v1 = acc[mt][nt][hf * 2 + 1];
                    v0 = (v0 - mu) * inv * sm->gam[n]     + sm->bet[n];
                    v1 = (v1 - mu) * inv * sm->gam[n + 1] + sm->bet[n + 1];
                    if (HAS_RES) {
                        float2 rr = *(const float2*)(resid + (size_t)m * CDIM + n);
                        v0 += rr.x; v1 += rr.y;
                    }
                    v0 = gelu_exact(v0);
                    v1 = gelu_exact(v1);
                    if (HALF_OUT) {
                        __half2 h = __floats2half2_rn(v0, v1);
                        *(__half2*)((__half*)dst_v + (size_t)m * CDIM + n) = h;
                    } else {
                        *(float2*)((float*)dst_v + (size_t)m * CDIM + n) = make_float2(v0, v1);
                    }
                }
            }
        }
    }
}

// ---------------- launch (3 kernels) ----------------
extern "C" void kernel_launch(void* const* d_in, const int* in_sizes, int n_in,
                              void* d_out, int out_size) {
    const float* feats  = (const float*)d_in[0];
    const float* W1     = (const float*)d_in[1];
    const float* gamma1 = (const float*)d_in[2];
    const float* beta1  = (const float*)d_in[3];
    const float* W2     = (const float*)d_in[4];
    const float* gamma2 = (const float*)d_in[5];
    const float* beta2  = (const float*)d_in[6];
    const int*   nbr    = (const int*)d_in[7];
    const void*  mask   = (const void*)d_in[8];

    __half *hfeats, *mid, *wt1, *wt2;
    cudaGetSymbolAddress((void**)&hfeats, g_hfeats);
    cudaGetSymbolAddress((void**)&mid, g_mid);
    cudaGetSymbolAddress((void**)&wt1, g_WT1);
    cudaGetSymbolAddress((void**)&wt2, g_WT2);

    const int smem_bytes = (int)sizeof(Smem);
    cudaFuncSetAttribute(conv_mma<false, true>, cudaFuncAttributeMaxDynamicSharedMemorySize, smem_bytes);
    cudaFuncSetAttribute(conv_mma<true, false>, cudaFuncAttributeMaxDynamicSharedMemorySize, smem_bytes);

    prepass_kernel<<<PRE_BLOCKS, THREADS>>>(feats, W1, W2, nbr, mask, hfeats, wt1, wt2);

    const int grid = (NPTS + BM - 1) / BM;  // 1563
    conv_mma<false, true><<<grid, THREADS, smem_bytes>>>(hfeats, wt1, gamma1, beta1, nullptr, mid);
    conv_mma<true, false><<<grid, THREADS, smem_bytes>>>(mid,  wt2, gamma2, beta2, feats, d_out);
}

// round 15
// speedup vs baseline: 1.4968x; 1.0051x over previous
#include <cuda_runtime.h>
#include <cuda_fp16.h>
#include <cstdint>
#include <math.h>

// ---------------- problem constants ----------------
#define NPTS 100000
#define KNBR 9
#define CDIM 256
#define BM   64                   // rows per CTA
#define THREADS 256               // 8 warps: 2 (M) x 4 (N), warp tile 32x64
#define NKT  36                   // 9 neighbors * 256/64
#define NSTG 2                    // cp.async pipeline depth
#define RS   72                   // smem row stride in halves (64 + 8 pad = 144B)
#define A_STG_B (BM * RS * 2)     // 9216
#define B_STG_B (CDIM * RS * 2)   // 36864

// fused pre-pass block ranges (f2h FIRST: it is the longest stream)
#define F2H_BLOCKS 2048
#define TR_BLOCKS  1152           // 8 x 8 x 18 transpose tiles
#define NBR_BLOCKS 879            // ceil((900000/4)/256)
#define TR_BASE    F2H_BLOCKS
#define NBR_BASE   (F2H_BLOCKS + TR_BLOCKS)
#define PRE_BLOCKS (F2H_BLOCKS + TR_BLOCKS + NBR_BLOCKS)

// ---------------- scratch ----------------
__device__ int    g_nbr[NPTS * KNBR];
__device__ __half g_hfeats[(size_t)NPTS * CDIM];
__device__ __half g_mid[(size_t)NPTS * CDIM];
__device__ __half g_WT1[KNBR * CDIM * CDIM];   // [kk][d][c] (n-major), fp16
__device__ __half g_WT2[KNBR * CDIM * CDIM];

// ---------------- smem (conv) ----------------
struct Smem {
    __half As[NSTG][BM][RS];      // 18432 B
    __half Bs[NSTG][CDIM][RS];    // 73728 B
    int    nbr[BM * KNBR];        //  2304 B
    float  gam[CDIM], bet[CDIM];  //  2048 B
    float  red1[BM][4], red2[BM][4];
    float  mu[BM], inv[BM];
};                                 // ~99 KB -> 2 CTAs/SM

// ---------------- helpers ----------------
__device__ __forceinline__ void cp16(uint32_t dst, const void* src, uint32_t sz) {
    asm volatile("cp.async.cg.shared.global [%0], [%1], 16, %2;"
                 :: "r"(dst), "l"(src), "r"(sz) : "memory");
}
#define CP_COMMIT() asm volatile("cp.async.commit_group;" ::: "memory")
#define CP_WAIT0()  asm volatile("cp.async.wait_group 0;" ::: "memory")

__device__ __forceinline__ void ldsm4(uint32_t* r, uint32_t addr) {
    asm volatile("ldmatrix.sync.aligned.m8n8.x4.shared.b16 {%0,%1,%2,%3}, [%4];"
                 : "=r"(r[0]), "=r"(r[1]), "=r"(r[2]), "=r"(r[3]) : "r"(addr));
}
__device__ __forceinline__ void mma16(float* c, const uint32_t* a, uint32_t b0, uint32_t b1) {
    asm volatile(
        "mma.sync.aligned.m16n8k16.row.col.f32.f16.f16.f32 "
        "{%0,%1,%2,%3}, {%4,%5,%6,%7}, {%8,%9}, {%0,%1,%2,%3};"
        : "+f"(c[0]), "+f"(c[1]), "+f"(c[2]), "+f"(c[3])
        : "r"(a[0]), "r"(a[1]), "r"(a[2]), "r"(a[3]), "r"(b0), "r"(b1));
}
__device__ __forceinline__ float gelu_exact(float x) {
    return 0.5f * x * (1.0f + erff(x * 0.70710678118654752f));
}

// ---------------- fused pre-pass: f2h + transpose(W1,W2) + build_nbr ----------------
__global__ void prepass_kernel(const float* __restrict__ feats,
                               const float* __restrict__ W1,
                               const float* __restrict__ W2,
                               const int*   __restrict__ idx,
                               const void*  __restrict__ mask,
                               __half* __restrict__ hfeats,
                               __half* __restrict__ wt1,
                               __half* __restrict__ wt2) {
    const int b = blockIdx.x;
    const int tid = threadIdx.x;

    if (b < F2H_BLOCKS) {
        // ---- feats f32 -> f16 (largest stream: runs first) ----
        const int n4 = NPTS * CDIM / 4;
        for (int i = b * THREADS + tid; i < n4; i += F2H_BLOCKS * THREADS) {
            float4 v = __ldg((const float4*)feats + i);
            __half2 h0 = __floats2half2_rn(v.x, v.y);
            __half2 h1 = __floats2half2_rn(v.z, v.w);
            ((uint2*)hfeats)[i] = make_uint2(*(uint32_t*)&h0, *(uint32_t*)&h1);
        }
    } else if (b < NBR_BASE) {
        // ---- weight transpose: WT[kk][d][c] = (half)W[kk][c][d] ----
        __shared__ float t[32][33];
        const int bb  = b - TR_BASE;
        const int z   = bb >> 6;          // 0..17
        const int rem = bb & 63;
        const int c0  = (rem & 7) << 5;
        const int d0  = (rem >> 3) << 5;
        const int kk  = (z >= KNBR) ? z - KNBR : z;
        const float* Wk = ((z >= KNBR) ? W2 : W1) + (size_t)kk * 65536;
        __half* Tk = ((z >= KNBR) ? wt2 : wt1) + (size_t)kk * 65536;
        const int x = tid & 31, y = tid >> 5;   // y in 0..7
#pragma unroll
        for (int j = 0; j < 32; j += 8) t[y + j][x] = Wk[(c0 + y + j) * 256 + d0 + x];
        __syncthreads();
#pragma unroll
        for (int j = 0; j < 32; j += 8) Tk[(d0 + y + j) * 256 + c0 + x] = __float2half(t[x][y + j]);
    } else {
        // ---- neighbor table, 4-wide, with in-block mask-width detection ----
        __shared__ int flag;
        if (tid == 0) flag = 0;
        __syncthreads();
        const unsigned int* mw = (const unsigned int*)mask;
        for (int i = tid; i < 1024; i += THREADS) {
            unsigned w = mw[i];
            if (w != 0u && w != 1u && w != 0x3F800000u) flag = 1;  // u8-packed pattern
        }
        __syncthreads();
        const bool u8 = (flag != 0);
        const int i4 = (b - NBR_BASE) * THREADS + tid;
        if (i4 < NPTS * KNBR / 4) {
            int4 v = __ldg((const int4*)idx + i4);
            int4 r;
            if (u8) {
                uchar4 m4 = __ldg((const uchar4*)mask + i4);
                r.x = m4.x ? v.x : -1;
                r.y = m4.y ? v.y : -1;
                r.z = m4.z ? v.z : -1;
                r.w = m4.w ? v.w : -1;
            } else {
                uint4 m4 = __ldg((const uint4*)mask + i4);
                r.x = m4.x ? v.x : -1;
                r.y = m4.y ? v.y : -1;
                r.z = m4.z ? v.z : -1;
                r.w = m4.w ? v.w : -1;
            }
            ((int4*)g_nbr)[i4] = r;
        }
    }
}

// ---------------- stage loader (cp.async, 64-channel chunk, 256 thr) ----------------
__device__ __forceinline__ void issue_stage(Smem* sm, int st, int kt,
                                            const __half* __restrict__ src,
                                            const __half* __restrict__ WT, int tid) {
    const int kk = kt >> 2;            // neighbor slot
    const int cb = (kt & 3) << 6;      // channel base (halves)
    // A gather: 64 rows x 64 halves (128B/row); 4 threads/row, 2 x 16B each
    {
        const int row = tid >> 2, j = tid & 3;
        const int r = sm->nbr[row * KNBR + kk];
        const uint32_t sz = (r >= 0) ? 16u : 0u;
        const __half* gp = src + ((size_t)(r >= 0 ? r : 0) << 8) + cb;
        cp16((uint32_t)__cvta_generic_to_shared(&sm->As[st][row][j * 8]),      gp + j * 8,      sz);
        cp16((uint32_t)__cvta_generic_to_shared(&sm->As[st][row][j * 8 + 32]), gp + j * 8 + 32, sz);
    }
    // B: 256 n-rows x 64 halves; 8 x 16B per thread
    {
        const __half* wb = WT + ((size_t)kk << 16) + cb;
#pragma unroll
        for (int q = 0; q < 8; q++) {
            const int c = q * THREADS + tid;
            const int n = c >> 3, kq = c & 7;
            cp16((uint32_t)__cvta_generic_to_shared(&sm->Bs[st][n][kq * 8]),
                 wb + ((size_t)n << 8) + kq * 8, 16u);
        }
    }
}

// ---------------- fused fp16 mma conv + LN + GELU (+res) — R11-identical ----------------
template <bool HAS_RES, bool HALF_OUT>
__global__ __launch_bounds__(THREADS, 2)
void conv_mma(const __half* __restrict__ src, const __half* __restrict__ WT,
              const float* __restrict__ gamma, const float* __restrict__ beta,
              const float* __restrict__ resid, void* __restrict__ dst_v) {
    extern __shared__ unsigned char sm_raw[];
    Smem* sm = (Smem*)sm_raw;

    const int tid  = threadIdx.x;
    const int lane = tid & 31;
    const int wid  = tid >> 5;
    const int wm   = wid >> 2;  // 0..1: rows wm*32..+32
    const int wn   = wid & 3;   // 0..3: cols wn*64..+64
    const int m0   = blockIdx.x * BM;

    for (int i = tid; i < BM * KNBR; i += THREADS) {
        int m = m0 + i / KNBR;
        sm->nbr[i] = (m < NPTS) ? g_nbr[(size_t)m * KNBR + (i % KNBR)] : -1;
    }
    if (tid < CDIM) { sm->gam[tid] = gamma[tid]; sm->bet[tid] = beta[tid]; }
    __syncthreads();

    // ---- ldmatrix lane addresses ----
    uint32_t aAddr[2];
    {
        const int rowsel = ((lane >> 3) & 1) * 8 + (lane & 7);
        const int kboff  = (lane >> 4) * 16;
#pragma unroll
        for (int mt = 0; mt < 2; mt++) {
            const int arow = wm * 32 + mt * 16 + rowsel;
            aAddr[mt] = (uint32_t)__cvta_generic_to_shared(&sm->As[0][0][0])
                        + (uint32_t)(arow * (RS * 2) + kboff);
        }
    }
    uint32_t bAddr[4];
    {
        const int nrowsel = ((lane >> 4) & 1) * 8 + (lane & 7);
        const int kboff   = ((lane >> 3) & 1) * 16;
#pragma unroll
        for (int p = 0; p < 4; p++) {
            const int brow = wn * 64 + p * 16 + nrowsel;
            bAddr[p] = (uint32_t)__cvta_generic_to_shared(&sm->Bs[0][0][0])
                       + (uint32_t)(brow * (RS * 2) + kboff);
        }
    }

    // prologue: stage 0
    issue_stage(sm, 0, 0, src, WT, tid);
    CP_COMMIT();

    float acc[2][8][4];
#pragma unroll
    for (int mt = 0; mt < 2; mt++)
#pragma unroll
        for (int nt = 0; nt < 8; nt++)
#pragma unroll
            for (int e = 0; e < 4; e++) acc[mt][nt][e] = 0.0f;

    int cur = 0;
    for (int kt = 0; kt < NKT; ++kt) {
        CP_WAIT0();
        __syncthreads();

        if (kt + 1 < NKT)
            issue_stage(sm, cur ^ 1, kt + 1, src, WT, tid);
        CP_COMMIT();

        const uint32_t ao = (uint32_t)cur * A_STG_B;
        const uint32_t bo = (uint32_t)cur * B_STG_B;
#pragma unroll
        for (int ks = 0; ks < 4; ks++) {
            uint32_t af0[4], af1[4];
            ldsm4(af0, aAddr[0] + ao + ks * 32);
            ldsm4(af1, aAddr[1] + ao + ks * 32);
#pragma unroll
            for (int p = 0; p < 4; p++) {
                uint32_t bf[4];
                ldsm4(bf, bAddr[p] + bo + ks * 32);
                mma16(acc[0][2 * p],     af0, bf[0], bf[1]);
                mma16(acc[1][2 * p],     af1, bf[0], bf[1]);
                mma16(acc[0][2 * p + 1], af0, bf[2], bf[3]);
                mma16(acc[1][2 * p + 1], af1, bf[2], bf[3]);
            }
        }
        cur ^= 1;
    }

    // ---- LayerNorm reduction ----
    __syncthreads();
#pragma unroll
    for (int mt = 0; mt < 2; mt++) {
        float s1a = 0.f, s2a = 0.f, s1b = 0.f, s2b = 0.f;
#pragma unroll
        for (int nt = 0; nt < 8; nt++) {
            float v0 = acc[mt][nt][0], v1 = acc[mt][nt][1];
            float v2 = acc[mt][nt][2], v3 = acc[mt][nt][3];
            s1a += v0 + v1; s2a += v0 * v0 + v1 * v1;
            s1b += v2 + v3; s2b += v2 * v2 + v3 * v3;
        }
#pragma unroll
        for (int o = 1; o < 4; o <<= 1) {
            s1a += __shfl_xor_sync(0xFFFFFFFFu, s1a, o);
            s2a += __shfl_xor_sync(0xFFFFFFFFu, s2a, o);
            s1b += __shfl_xor_sync(0xFFFFFFFFu, s1b, o);
            s2b += __shfl_xor_sync(0xFFFFFFFFu, s2b, o);
        }
        if ((lane & 3) == 0) {
            int r = (wm << 5) + (mt << 4) + (lane >> 2);
            sm->red1[r][wn] = s1a; sm->red2[r][wn] = s2a;
            sm->red1[r + 8][wn] = s1b; sm->red2[r + 8][wn] = s2b;
        }
    }
    __syncthreads();
    if (tid < BM) {
        float s1 = sm->red1[tid][0] + sm->red1[tid][1] + sm->red1[tid][2] + sm->red1[tid][3];
        float s2 = sm->red2[tid][0] + sm->red2[tid][1] + sm->red2[tid][2] + sm->red2[tid][3];
        float mu  = s1 * (1.0f / 256.0f);
        float var = s2 * (1.0f / 256.0f) - mu * mu;
        sm->mu[tid]  = mu;
        sm->inv[tid] = rsqrtf(var + 1e-6f);
    }
    __syncthreads();

    // ---- normalize + residual + GELU + store ----
#pragma unroll
    for (int mt = 0; mt < 2; mt++) {
#pragma unroll
        for (int hf = 0; hf < 2; hf++) {
            int r = (wm << 5) + (mt << 4) + (lane >> 2) + hf * 8;
            int m = m0 + r;
            if (m < NPTS) {
                float mu = sm->mu[r], inv = sm->inv[r];
#pragma unroll
                for (int nt = 0; nt < 8; nt++) {
                    int n = (wn << 6) + nt * 8 + ((lane & 3) << 1);
                    float v0 = acc[mt][nt][hf * 2 + 0];
                    float v1 = acc[mt][nt][hf * 2 + 1];
                    v0 = (v0 - mu) * inv * sm->gam[n]     + sm->bet[n];
                    v1 = (v1 - mu) * inv * sm->gam[n + 1] + sm->bet[n + 1];
                    if (HAS_RES) {
                        float2 rr = *(const float2*)(resid + (size_t)m * CDIM + n);
                        v0 += rr.x; v1 += rr.y;
                    }
                    v0 = gelu_exact(v0);
                    v1 = gelu_exact(v1);
                    if (HALF_OUT) {
                        __half2 h = __floats2half2_rn(v0, v1);
                        *(__half2*)((__half*)dst_v + (size_t)m * CDIM + n) = h;
                    } else {
                        *(float2*)((float*)dst_v + (size_t)m * CDIM + n) = make_float2(v0, v1);
                    }
                }
            }
        }
    }
}

// ---------------- launch (3 kernels) ----------------
extern "C" void kernel_launch(void* const* d_in, const int* in_sizes, int n_in,
                              void* d_out, int out_size) {
    const float* feats  = (const float*)d_in[0];
    const float* W1     = (const float*)d_in[1];
    const float* gamma1 = (const float*)d_in[2];
    const float* beta1  = (const float*)d_in[3];
    const float* W2     = (const float*)d_in[4];
    const float* gamma2 = (const float*)d_in[5];
    const float* beta2  = (const float*)d_in[6];
    const int*   nbr    = (const int*)d_in[7];
    const void*  mask   = (const void*)d_in[8];

    __half *hfeats, *mid, *wt1, *wt2;
    cudaGetSymbolAddress((void**)&hfeats, g_hfeats);
    cudaGetSymbolAddress((void**)&mid, g_mid);
    cudaGetSymbolAddress((void**)&wt1, g_WT1);
    cudaGetSymbolAddress((void**)&wt2, g_WT2);

    const int smem_bytes = (int)sizeof(Smem);
    cudaFuncSetAttribute(conv_mma<false, true>, cudaFuncAttributeMaxDynamicSharedMemorySize, smem_bytes);
    cudaFuncSetAttribute(conv_mma<true, false>, cudaFuncAttributeMaxDynamicSharedMemorySize, smem_bytes);

    prepass_kernel<<<PRE_BLOCKS, THREADS>>>(feats, W1, W2, nbr, mask, hfeats, wt1, wt2);

    const int grid = (NPTS + BM - 1) / BM;  // 1563
    conv_mma<false, true><<<grid, THREADS, smem_bytes>>>(hfeats, wt1, gamma1, beta1, nullptr, mid);
    conv_mma<true, false><<<grid, THREADS, smem_bytes>>>(mid,  wt2, gamma2, beta2, feats, d_out);
}

// round 16
// speedup vs baseline: 1.5004x; 1.0024x over previous
#include <cuda_runtime.h>
#include <cuda_fp16.h>
#include <cstdint>
#include <math.h>

// ---------------- problem constants ----------------
#define NPTS 100000
#define KNBR 9
#define CDIM 256
#define BM   64                   // rows per CTA
#define THREADS 256               // 8 warps: 2 (M) x 4 (N), warp tile 32x64
#define NKT  36                   // 9 neighbors * 256/64
#define NSTG 2                    // cp.async pipeline depth
#define RS   72                   // smem row stride in halves (64 + 8 pad = 144B)
#define A_STG_B (BM * RS * 2)     // 9216
#define B_STG_B (CDIM * RS * 2)   // 36864

// fused pre-pass block ranges (f2h FIRST: longest stream, one resident wave)
#define F2H_BLOCKS 1184           // 148 SMs x 8 blocks
#define TR_BLOCKS  1152           // 8 x 8 x 18 transpose tiles
#define NBR_BLOCKS 879            // ceil((900000/4)/256)
#define TR_BASE    F2H_BLOCKS
#define NBR_BASE   (F2H_BLOCKS + TR_BLOCKS)
#define PRE_BLOCKS (F2H_BLOCKS + TR_BLOCKS + NBR_BLOCKS)

// ---------------- scratch ----------------
__device__ int    g_nbr[NPTS * KNBR];
__device__ __half g_hfeats[(size_t)NPTS * CDIM];
__device__ __half g_mid[(size_t)NPTS * CDIM];
__device__ __half g_WT1[KNBR * CDIM * CDIM];   // [kk][d][c] (n-major), fp16
__device__ __half g_WT2[KNBR * CDIM * CDIM];

// ---------------- smem (conv) ----------------
struct Smem {
    __half As[NSTG][BM][RS];      // 18432 B
    __half Bs[NSTG][CDIM][RS];    // 73728 B
    int    nbr[BM * KNBR];        //  2304 B
    float  gam[CDIM], bet[CDIM];  //  2048 B
    float  red1[BM][4], red2[BM][4];
    float  mu[BM], inv[BM];
};                                 // ~99 KB -> 2 CTAs/SM

// ---------------- helpers ----------------
__device__ __forceinline__ void cp16(uint32_t dst, const void* src, uint32_t sz) {
    asm volatile("cp.async.cg.shared.global [%0], [%1], 16, %2;"
                 :: "r"(dst), "l"(src), "r"(sz) : "memory");
}
#define CP_COMMIT() asm volatile("cp.async.commit_group;" ::: "memory")
#define CP_WAIT0()  asm volatile("cp.async.wait_group 0;" ::: "memory")

__device__ __forceinline__ void ldsm4(uint32_t* r, uint32_t addr) {
    asm volatile("ldmatrix.sync.aligned.m8n8.x4.shared.b16 {%0,%1,%2,%3}, [%4];"
                 : "=r"(r[0]), "=r"(r[1]), "=r"(r[2]), "=r"(r[3]) : "r"(addr));
}
__device__ __forceinline__ void mma16(float* c, const uint32_t* a, uint32_t b0, uint32_t b1) {
    asm volatile(
        "mma.sync.aligned.m16n8k16.row.col.f32.f16.f16.f32 "
        "{%0,%1,%2,%3}, {%4,%5,%6,%7}, {%8,%9}, {%0,%1,%2,%3};"
        : "+f"(c[0]), "+f"(c[1]), "+f"(c[2]), "+f"(c[3])
        : "r"(a[0]), "r"(a[1]), "r"(a[2]), "r"(a[3]), "r"(b0), "r"(b1));
}
__device__ __forceinline__ float gelu_exact(float x) {
    return 0.5f * x * (1.0f + erff(x * 0.70710678118654752f));
}

// ---------------- fused pre-pass: f2h + transpose(W1,W2) + build_nbr ----------------
__global__ void prepass_kernel(const float* __restrict__ feats,
                               const float* __restrict__ W1,
                               const float* __restrict__ W2,
                               const int*   __restrict__ idx,
                               const void*  __restrict__ mask,
                               __half* __restrict__ hfeats,
                               __half* __restrict__ wt1,
                               __half* __restrict__ wt2) {
    const int b = blockIdx.x;
    const int tid = threadIdx.x;

    if (b < F2H_BLOCKS) {
        // ---- feats f32 -> f16, unrolled x4 for MLP (4 outstanding loads) ----
        const int n4 = NPTS * CDIM / 4;                 // 6,400,000 float4 elems
        const int stride = F2H_BLOCKS * THREADS;        // 303,104
        int i = b * THREADS + tid;
        for (; i + 3 * stride < n4; i += 4 * stride) {
            float4 v0 = __ldg((const float4*)feats + i);
            float4 v1 = __ldg((const float4*)feats + i + stride);
            float4 v2 = __ldg((const float4*)feats + i + 2 * stride);
            float4 v3 = __ldg((const float4*)feats + i + 3 * stride);
            __half2 a0 = __floats2half2_rn(v0.x, v0.y), b0 = __floats2half2_rn(v0.z, v0.w);
            __half2 a1 = __floats2half2_rn(v1.x, v1.y), b1 = __floats2half2_rn(v1.z, v1.w);
            __half2 a2 = __floats2half2_rn(v2.x, v2.y), b2 = __floats2half2_rn(v2.z, v2.w);
            __half2 a3 = __floats2half2_rn(v3.x, v3.y), b3 = __floats2half2_rn(v3.z, v3.w);
            ((uint2*)hfeats)[i]              = make_uint2(*(uint32_t*)&a0, *(uint32_t*)&b0);
            ((uint2*)hfeats)[i + stride]     = make_uint2(*(uint32_t*)&a1, *(uint32_t*)&b1);
            ((uint2*)hfeats)[i + 2 * stride] = make_uint2(*(uint32_t*)&a2, *(uint32_t*)&b2);
            ((uint2*)hfeats)[i + 3 * stride] = make_uint2(*(uint32_t*)&a3, *(uint32_t*)&b3);
        }
        for (; i < n4; i += stride) {
            float4 v = __ldg((const float4*)feats + i);
            __half2 h0 = __floats2half2_rn(v.x, v.y);
            __half2 h1 = __floats2half2_rn(v.z, v.w);
            ((uint2*)hfeats)[i] = make_uint2(*(uint32_t*)&h0, *(uint32_t*)&h1);
        }
    } else if (b < NBR_BASE) {
        // ---- weight transpose: WT[kk][d][c] = (half)W[kk][c][d] ----
        __shared__ float t[32][33];
        const int bb  = b - TR_BASE;
        const int z   = bb >> 6;          // 0..17
        const int rem = bb & 63;
        const int c0  = (rem & 7) << 5;
        const int d0  = (rem >> 3) << 5;
        const int kk  = (z >= KNBR) ? z - KNBR : z;
        const float* Wk = ((z >= KNBR) ? W2 : W1) + (size_t)kk * 65536;
        __half* Tk = ((z >= KNBR) ? wt2 : wt1) + (size_t)kk * 65536;
        const int x = tid & 31, y = tid >> 5;   // y in 0..7
#pragma unroll
        for (int j = 0; j < 32; j += 8) t[y + j][x] = Wk[(c0 + y + j) * 256 + d0 + x];
        __syncthreads();
#pragma unroll
        for (int j = 0; j < 32; j += 8) Tk[(d0 + y + j) * 256 + c0 + x] = __float2half(t[x][y + j]);
    } else {
        // ---- neighbor table, 4-wide, with in-block mask-width detection ----
        __shared__ int flag;
        if (tid == 0) flag = 0;
        __syncthreads();
        const unsigned int* mw = (const unsigned int*)mask;
        for (int i = tid; i < 1024; i += THREADS) {
            unsigned w = mw[i];
            if (w != 0u && w != 1u && w != 0x3F800000u) flag = 1;  // u8-packed pattern
        }
        __syncthreads();
        const bool u8 = (flag != 0);
        const int i4 = (b - NBR_BASE) * THREADS + tid;
        if (i4 < NPTS * KNBR / 4) {
            int4 v = __ldg((const int4*)idx + i4);
            int4 r;
            if (u8) {
                uchar4 m4 = __ldg((const uchar4*)mask + i4);
                r.x = m4.x ? v.x : -1;
                r.y = m4.y ? v.y : -1;
                r.z = m4.z ? v.z : -1;
                r.w = m4.w ? v.w : -1;
            } else {
                uint4 m4 = __ldg((const uint4*)mask + i4);
                r.x = m4.x ? v.x : -1;
                r.y = m4.y ? v.y : -1;
                r.z = m4.z ? v.z : -1;
                r.w = m4.w ? v.w : -1;
            }
            ((int4*)g_nbr)[i4] = r;
        }
    }
}

// ---------------- stage loader (cp.async, 64-channel chunk, 256 thr) ----------------
__device__ __forceinline__ void issue_stage(Smem* sm, int st, int kt,
                                            const __half* __restrict__ src,
                                            const __half* __restrict__ WT, int tid) {
    const int kk = kt >> 2;            // neighbor slot
    const int cb = (kt & 3) << 6;      // channel base (halves)
    // A gather: 64 rows x 64 halves (128B/row); 4 threads/row, 2 x 16B each
    {
        const int row = tid >> 2, j = tid & 3;
        const int r = sm->nbr[row * KNBR + kk];
        const uint32_t sz = (r >= 0) ? 16u : 0u;
        const __half* gp = src + ((size_t)(r >= 0 ? r : 0) << 8) + cb;
        cp16((uint32_t)__cvta_generic_to_shared(&sm->As[st][row][j * 8]),      gp + j * 8,      sz);
        cp16((uint32_t)__cvta_generic_to_shared(&sm->As[st][row][j * 8 + 32]), gp + j * 8 + 32, sz);
    }
    // B: 256 n-rows x 64 halves; 8 x 16B per thread
    {
        const __half* wb = WT + ((size_t)kk << 16) + cb;
#pragma unroll
        for (int q = 0; q < 8; q++) {
            const int c = q * THREADS + tid;
            const int n = c >> 3, kq = c & 7;
            cp16((uint32_t)__cvta_generic_to_shared(&sm->Bs[st][n][kq * 8]),
                 wb + ((size_t)n << 8) + kq * 8, 16u);
        }
    }
}

// ---------------- fused fp16 mma conv + LN + GELU (+res) — R11-identical ----------------
template <bool HAS_RES, bool HALF_OUT>
__global__ __launch_bounds__(THREADS, 2)
void conv_mma(const __half* __restrict__ src, const __half* __restrict__ WT,
              const float* __restrict__ gamma, const float* __restrict__ beta,
              const float* __restrict__ resid, void* __restrict__ dst_v) {
    extern __shared__ unsigned char sm_raw[];
    Smem* sm = (Smem*)sm_raw;

    const int tid  = threadIdx.x;
    const int lane = tid & 31;
    const int wid  = tid >> 5;
    const int wm   = wid >> 2;  // 0..1: rows wm*32..+32
    const int wn   = wid & 3;   // 0..3: cols wn*64..+64
    const int m0   = blockIdx.x * BM;

    for (int i = tid; i < BM * KNBR; i += THREADS) {
        int m = m0 + i / KNBR;
        sm->nbr[i] = (m < NPTS) ? g_nbr[(size_t)m * KNBR + (i % KNBR)] : -1;
    }
    if (tid < CDIM) { sm->gam[tid] = gamma[tid]; sm->bet[tid] = beta[tid]; }
    __syncthreads();

    // ---- ldmatrix lane addresses ----
    uint32_t aAddr[2];
    {
        const int rowsel = ((lane >> 3) & 1) * 8 + (lane & 7);
        const int kboff  = (lane >> 4) * 16;
#pragma unroll
        for (int mt = 0; mt < 2; mt++) {
            const int arow = wm * 32 + mt * 16 + rowsel;
            aAddr[mt] = (uint32_t)__cvta_generic_to_shared(&sm->As[0][0][0])
                        + (uint32_t)(arow * (RS * 2) + kboff);
        }
    }
    uint32_t bAddr[4];
    {
        const int nrowsel = ((lane >> 4) & 1) * 8 + (lane & 7);
        const int kboff   = ((lane >> 3) & 1) * 16;
#pragma unroll
        for (int p = 0; p < 4; p++) {
            const int brow = wn * 64 + p * 16 + nrowsel;
            bAddr[p] = (uint32_t)__cvta_generic_to_shared(&sm->Bs[0][0][0])
                       + (uint32_t)(brow * (RS * 2) + kboff);
        }
    }

    // prologue: stage 0
    issue_stage(sm, 0, 0, src, WT, tid);
    CP_COMMIT();

    float acc[2][8][4];
#pragma unroll
    for (int mt = 0; mt < 2; mt++)
#pragma unroll
        for (int nt = 0; nt < 8; nt++)
#pragma unroll
            for (int e = 0; e < 4; e++) acc[mt][nt][e] = 0.0f;

    int cur = 0;
    for (int kt = 0; kt < NKT; ++kt) {
        CP_WAIT0();
        __syncthreads();

        if (kt + 1 < NKT)
            issue_stage(sm, cur ^ 1, kt + 1, src, WT, tid);
        CP_COMMIT();

        const uint32_t ao = (uint32_t)cur * A_STG_B;
        const uint32_t bo = (uint32_t)cur * B_STG_B;
#pragma unroll
        for (int ks = 0; ks < 4; ks++) {
            uint32_t af0[4], af1[4];
            ldsm4(af0, aAddr[0] + ao + ks * 32);
            ldsm4(af1, aAddr[1] + ao + ks * 32);
#pragma unroll
            for (int p = 0; p < 4; p++) {
                uint32_t bf[4];
                ldsm4(bf, bAddr[p] + bo + ks * 32);
                mma16(acc[0][2 * p],     af0, bf[0], bf[1]);
                mma16(acc[1][2 * p],     af1, bf[0], bf[1]);
                mma16(acc[0][2 * p + 1], af0, bf[2], bf[3]);
                mma16(acc[1][2 * p + 1], af1, bf[2], bf[3]);
            }
        }
        cur ^= 1;
    }

    // ---- LayerNorm reduction ----
    __syncthreads();
#pragma unroll
    for (int mt = 0; mt < 2; mt++) {
        float s1a = 0.f, s2a = 0.f, s1b = 0.f, s2b = 0.f;
#pragma unroll
        for (int nt = 0; nt < 8; nt++) {
            float v0 = acc[mt][nt][0], v1 = acc[mt][nt][1];
            float v2 = acc[mt][nt][2], v3 = acc[mt][nt][3];
            s1a += v0 + v1; s2a += v0 * v0 + v1 * v1;
            s1b += v2 + v3; s2b += v2 * v2 + v3 * v3;
        }
#pragma unroll
        for (int o = 1; o < 4; o <<= 1) {
            s1a += __shfl_xor_sync(0xFFFFFFFFu, s1a, o);
            s2a += __shfl_xor_sync(0xFFFFFFFFu, s2a, o);
            s1b += __shfl_xor_sync(0xFFFFFFFFu, s1b, o);
            s2b += __shfl_xor_sync(0xFFFFFFFFu, s2b, o);
        }
        if ((lane & 3) == 0) {
            int r = (wm << 5) + (mt << 4) + (lane >> 2);
            sm->red1[r][wn] = s1a; sm->red2[r][wn] = s2a;
            sm->red1[r + 8][wn] = s1b; sm->red2[r + 8][wn] = s2b;
        }
    }
    __syncthreads();
    if (tid < BM) {
        float s1 = sm->red1[tid][0] + sm->red1[tid][1] + sm->red1[tid][2] + sm->red1[tid][3];
        float s2 = sm->red2[tid][0] + sm->red2[tid][1] + sm->red2[tid][2] + sm->red2[tid][3];
        float mu  = s1 * (1.0f / 256.0f);
        float var = s2 * (1.0f / 256.0f) - mu * mu;
        sm->mu[tid]  = mu;
        sm->inv[tid] = rsqrtf(var + 1e-6f);
    }
    __syncthreads();

    // ---- normalize + residual + GELU + store ----
#pragma unroll
    for (int mt = 0; mt < 2; mt++) {
#pragma unroll
        for (int hf = 0; hf < 2; hf++) {
            int r = (wm << 5) + (mt << 4) + (lane >> 2) + hf * 8;
            int m = m0 + r;
            if (m < NPTS) {
                float mu = sm->mu[r], inv = sm->inv[r];
#pragma unroll
                for (int nt = 0; nt < 8; nt++) {
                    int n = (wn << 6) + nt * 8 + ((lane & 3) << 1);
                    float v0 = acc[mt][nt][hf * 2 + 0];
                    float v1 = acc[mt][nt][hf * 2 + 1];
                    v0 = (v0 - mu) * inv * sm->gam[n]     + sm->bet[n];
                    v1 = (v1 - mu) * inv * sm->gam[n + 1] + sm->bet[n + 1];
                    if (HAS_RES) {
                        float2 rr = *(const float2*)(resid + (size_t)m * CDIM + n);
                        v0 += rr.x; v1 += rr.y;
                    }
                    v0 = gelu_exact(v0);
                    v1 = gelu_exact(v1);
                    if (HALF_OUT) {
                        __half2 h = __floats2half2_rn(v0, v1);
                        *(__half2*)((__half*)dst_v + (size_t)m * CDIM + n) = h;
                    } else {
                        *(float2*)((float*)dst_v + (size_t)m * CDIM + n) = make_float2(v0, v1);
                    }
                }
            }
        }
    }
}

// ---------------- launch (3 kernels) ----------------
extern "C" void kernel_launch(void* const* d_in, const int* in_sizes, int n_in,
                              void* d_out, int out_size) {
    const float* feats  = (const float*)d_in[0];
    const float* W1     = (const float*)d_in[1];
    const float* gamma1 = (const float*)d_in[2];
    const float* beta1  = (const float*)d_in[3];
    const float* W2     = (const float*)d_in[4];
    const float* gamma2 = (const float*)d_in[5];
    const float* beta2  = (const float*)d_in[6];
    const int*   nbr    = (const int*)d_in[7];
    const void*  mask   = (const void*)d_in[8];

    __half *hfeats, *mid, *wt1, *wt2;
    cudaGetSymbolAddress((void**)&hfeats, g_hfeats);
    cudaGetSymbolAddress((void**)&mid, g_mid);
    cudaGetSymbolAddress((void**)&wt1, g_WT1);
    cudaGetSymbolAddress((void**)&wt2, g_WT2);

    const int smem_bytes = (int)sizeof(Smem);
    cudaFuncSetAttribute(conv_mma<false, true>, cudaFuncAttributeMaxDynamicSharedMemorySize, smem_bytes);
    cudaFuncSetAttribute(conv_mma<true, false>, cudaFuncAttributeMaxDynamicSharedMemorySize, smem_bytes);

    prepass_kernel<<<PRE_BLOCKS, THREADS>>>(feats, W1, W2, nbr, mask, hfeats, wt1, wt2);

    const int grid = (NPTS + BM - 1) / BM;  // 1563
    conv_mma<false, true><<<grid, THREADS, smem_bytes>>>(hfeats, wt1, gamma1, beta1, nullptr, mid);
    conv_mma<true, false><<<grid, THREADS, smem_bytes>>>(mid,  wt2, gamma2, beta2, feats, d_out);
}

// round 17
// speedup vs baseline: 1.5057x; 1.0035x over previous
#include <cuda_runtime.h>
#include <cuda_fp16.h>
#include <cstdint>
#include <math.h>

// ---------------- problem constants ----------------
#define NPTS 100000
#define KNBR 9
#define CDIM 256
#define BM   64                   // rows per CTA
#define THREADS 256               // 8 warps: 2 (M) x 4 (N), warp tile 32x64
#define NKT  36                   // 9 neighbors * 256/64
#define NSTG 2                    // cp.async pipeline depth
#define RS   72                   // smem row stride in halves (64 + 8 pad = 144B)
#define A_STG_B (BM * RS * 2)     // 9216
#define B_STG_B (CDIM * RS * 2)   // 36864

// fused pre-pass block ranges (f2h FIRST: longest stream, one resident wave)
#define F2H_BLOCKS 1184           // 148 SMs x 8 blocks
#define TR_BLOCKS  1152           // 8 x 8 x 18 transpose tiles
#define NBR_BLOCKS 879            // ceil((900000/4)/256)
#define TR_BASE    F2H_BLOCKS
#define NBR_BASE   (F2H_BLOCKS + TR_BLOCKS)
#define PRE_BLOCKS (F2H_BLOCKS + TR_BLOCKS + NBR_BLOCKS)

// ---------------- scratch ----------------
__device__ int    g_nbr[NPTS * KNBR];
__device__ __half g_hfeats[(size_t)NPTS * CDIM];
__device__ __half g_mid[(size_t)NPTS * CDIM];
__device__ __half g_WT1[KNBR * CDIM * CDIM];   // [kk][d][c] (n-major), fp16
__device__ __half g_WT2[KNBR * CDIM * CDIM];

// ---------------- smem (conv) ----------------
struct Smem {
    __half As[NSTG][BM][RS];      // 18432 B
    __half Bs[NSTG][CDIM][RS];    // 73728 B
    int    nbr[BM * KNBR];        //  2304 B
    float  gam[CDIM], bet[CDIM];  //  2048 B
    float  red1[BM][4], red2[BM][4];
    float  mu[BM], inv[BM];
};                                 // ~99 KB -> 2 CTAs/SM

// ---------------- helpers ----------------
__device__ __forceinline__ void cp16(uint32_t dst, const void* src, uint32_t sz) {
    asm volatile("cp.async.cg.shared.global [%0], [%1], 16, %2;"
                 :: "r"(dst), "l"(src), "r"(sz) : "memory");
}
#define CP_COMMIT() asm volatile("cp.async.commit_group;" ::: "memory")
#define CP_WAIT0()  asm volatile("cp.async.wait_group 0;" ::: "memory")

__device__ __forceinline__ void ldsm4(uint32_t* r, uint32_t addr) {
    asm volatile("ldmatrix.sync.aligned.m8n8.x4.shared.b16 {%0,%1,%2,%3}, [%4];"
                 : "=r"(r[0]), "=r"(r[1]), "=r"(r[2]), "=r"(r[3]) : "r"(addr));
}
__device__ __forceinline__ void mma16(float* c, const uint32_t* a, uint32_t b0, uint32_t b1) {
    asm volatile(
        "mma.sync.aligned.m16n8k16.row.col.f32.f16.f16.f32 "
        "{%0,%1,%2,%3}, {%4,%5,%6,%7}, {%8,%9}, {%0,%1,%2,%3};"
        : "+f"(c[0]), "+f"(c[1]), "+f"(c[2]), "+f"(c[3])
        : "r"(a[0]), "r"(a[1]), "r"(a[2]), "r"(a[3]), "r"(b0), "r"(b1));
}
__device__ __forceinline__ float gelu_exact(float x) {
    return 0.5f * x * (1.0f + erff(x * 0.70710678118654752f));
}

// ---------------- fused pre-pass: f2h + transpose(W1,W2) + build_nbr ----------------
__global__ void prepass_kernel(const float* __restrict__ feats,
                               const float* __restrict__ W1,
                               const float* __restrict__ W2,
                               const int*   __restrict__ idx,
                               const void*  __restrict__ mask,
                               __half* __restrict__ hfeats,
                               __half* __restrict__ wt1,
                               __half* __restrict__ wt2) {
    const int b = blockIdx.x;
    const int tid = threadIdx.x;

    if (b < F2H_BLOCKS) {
        // ---- feats f32 -> f16, unrolled x8, evict-first reads ----
        const int n4 = NPTS * CDIM / 4;                 // 6,400,000 float4 elems
        const int stride = F2H_BLOCKS * THREADS;        // 303,104
        int i = b * THREADS + tid;
        for (; i + 7 * stride < n4; i += 8 * stride) {
            float4 v[8];
#pragma unroll
            for (int q = 0; q < 8; q++)
                v[q] = __ldcs((const float4*)feats + i + q * stride);
#pragma unroll
            for (int q = 0; q < 8; q++) {
                __half2 h0 = __floats2half2_rn(v[q].x, v[q].y);
                __half2 h1 = __floats2half2_rn(v[q].z, v[q].w);
                ((uint2*)hfeats)[i + q * stride] =
                    make_uint2(*(uint32_t*)&h0, *(uint32_t*)&h1);
            }
        }
        for (; i < n4; i += stride) {
            float4 v = __ldcs((const float4*)feats + i);
            __half2 h0 = __floats2half2_rn(v.x, v.y);
            __half2 h1 = __floats2half2_rn(v.z, v.w);
            ((uint2*)hfeats)[i] = make_uint2(*(uint32_t*)&h0, *(uint32_t*)&h1);
        }
    } else if (b < NBR_BASE) {
        // ---- weight transpose: WT[kk][d][c] = (half)W[kk][c][d] ----
        __shared__ float t[32][33];
        const int bb  = b - TR_BASE;
        const int z   = bb >> 6;          // 0..17
        const int rem = bb & 63;
        const int c0  = (rem & 7) << 5;
        const int d0  = (rem >> 3) << 5;
        const int kk  = (z >= KNBR) ? z - KNBR : z;
        const float* Wk = ((z >= KNBR) ? W2 : W1) + (size_t)kk * 65536;
        __half* Tk = ((z >= KNBR) ? wt2 : wt1) + (size_t)kk * 65536;
        const int x = tid & 31, y = tid >> 5;   // y in 0..7
#pragma unroll
        for (int j = 0; j < 32; j += 8) t[y + j][x] = Wk[(c0 + y + j) * 256 + d0 + x];
        __syncthreads();
#pragma unroll
        for (int j = 0; j < 32; j += 8) Tk[(d0 + y + j) * 256 + c0 + x] = __float2half(t[x][y + j]);
    } else {
        // ---- neighbor table, 4-wide, with in-block mask-width detection ----
        __shared__ int flag;
        if (tid == 0) flag = 0;
        __syncthreads();
        const unsigned int* mw = (const unsigned int*)mask;
        for (int i = tid; i < 1024; i += THREADS) {
            unsigned w = mw[i];
            if (w != 0u && w != 1u && w != 0x3F800000u) flag = 1;  // u8-packed pattern
        }
        __syncthreads();
        const bool u8 = (flag != 0);
        const int i4 = (b - NBR_BASE) * THREADS + tid;
        if (i4 < NPTS * KNBR / 4) {
            int4 v = __ldg((const int4*)idx + i4);
            int4 r;
            if (u8) {
                uchar4 m4 = __ldg((const uchar4*)mask + i4);
                r.x = m4.x ? v.x : -1;
                r.y = m4.y ? v.y : -1;
                r.z = m4.z ? v.z : -1;
                r.w = m4.w ? v.w : -1;
            } else {
                uint4 m4 = __ldg((const uint4*)mask + i4);
                r.x = m4.x ? v.x : -1;
                r.y = m4.y ? v.y : -1;
                r.z = m4.z ? v.z : -1;
                r.w = m4.w ? v.w : -1;
            }
            ((int4*)g_nbr)[i4] = r;
        }
    }
}

// ---------------- stage loader (cp.async, 64-channel chunk, 256 thr) ----------------
__device__ __forceinline__ void issue_stage(Smem* sm, int st, int kt,
                                            const __half* __restrict__ src,
                                            const __half* __restrict__ WT, int tid) {
    const int kk = kt >> 2;            // neighbor slot
    const int cb = (kt & 3) << 6;      // channel base (halves)
    // A gather: 64 rows x 64 halves (128B/row); 4 threads/row, 2 x 16B each
    {
        const int row = tid >> 2, j = tid & 3;
        const int r = sm->nbr[row * KNBR + kk];
        const uint32_t sz = (r >= 0) ? 16u : 0u;
        const __half* gp = src + ((size_t)(r >= 0 ? r : 0) << 8) + cb;
        cp16((uint32_t)__cvta_generic_to_shared(&sm->As[st][row][j * 8]),      gp + j * 8,      sz);
        cp16((uint32_t)__cvta_generic_to_shared(&sm->As[st][row][j * 8 + 32]), gp + j * 8 + 32, sz);
    }
    // B: 256 n-rows x 64 halves; 8 x 16B per thread
    {
        const __half* wb = WT + ((size_t)kk << 16) + cb;
#pragma unroll
        for (int q = 0; q < 8; q++) {
            const int c = q * THREADS + tid;
            const int n = c >> 3, kq = c & 7;
            cp16((uint32_t)__cvta_generic_to_shared(&sm->Bs[st][n][kq * 8]),
                 wb + ((size_t)n << 8) + kq * 8, 16u);
        }
    }
}

// ---------------- fused fp16 mma conv + LN + GELU (+res) — R11-identical ----------------
template <bool HAS_RES, bool HALF_OUT>
__global__ __launch_bounds__(THREADS, 2)
void conv_mma(const __half* __restrict__ src, const __half* __restrict__ WT,
              const float* __restrict__ gamma, const float* __restrict__ beta,
              const float* __restrict__ resid, void* __restrict__ dst_v) {
    extern __shared__ unsigned char sm_raw[];
    Smem* sm = (Smem*)sm_raw;

    const int tid  = threadIdx.x;
    const int lane = tid & 31;
    const int wid  = tid >> 5;
    const int wm   = wid >> 2;  // 0..1: rows wm*32..+32
    const int wn   = wid & 3;   // 0..3: cols wn*64..+64
    const int m0   = blockIdx.x * BM;

    for (int i = tid; i < BM * KNBR; i += THREADS) {
        int m = m0 + i / KNBR;
        sm->nbr[i] = (m < NPTS) ? g_nbr[(size_t)m * KNBR + (i % KNBR)] : -1;
    }
    if (tid < CDIM) { sm->gam[tid] = gamma[tid]; sm->bet[tid] = beta[tid]; }
    __syncthreads();

    // ---- ldmatrix lane addresses ----
    uint32_t aAddr[2];
    {
        const int rowsel = ((lane >> 3) & 1) * 8 + (lane & 7);
        const int kboff  = (lane >> 4) * 16;
#pragma unroll
        for (int mt = 0; mt < 2; mt++) {
            const int arow = wm * 32 + mt * 16 + rowsel;
            aAddr[mt] = (uint32_t)__cvta_generic_to_shared(&sm->As[0][0][0])
                        + (uint32_t)(arow * (RS * 2) + kboff);
        }
    }
    uint32_t bAddr[4];
    {
        const int nrowsel = ((lane >> 4) & 1) * 8 + (lane & 7);
        const int kboff   = ((lane >> 3) & 1) * 16;
#pragma unroll
        for (int p = 0; p < 4; p++) {
            const int brow = wn * 64 + p * 16 + nrowsel;
            bAddr[p] = (uint32_t)__cvta_generic_to_shared(&sm->Bs[0][0][0])
                       + (uint32_t)(brow * (RS * 2) + kboff);
        }
    }

    // prologue: stage 0
    issue_stage(sm, 0, 0, src, WT, tid);
    CP_COMMIT();

    float acc[2][8][4];
#pragma unroll
    for (int mt = 0; mt < 2; mt++)
#pragma unroll
        for (int nt = 0; nt < 8; nt++)
#pragma unroll
            for (int e = 0; e < 4; e++) acc[mt][nt][e] = 0.0f;

    int cur = 0;
    for (int kt = 0; kt < NKT; ++kt) {
        CP_WAIT0();
        __syncthreads();

        if (kt + 1 < NKT)
            issue_stage(sm, cur ^ 1, kt + 1, src, WT, tid);
        CP_COMMIT();

        const uint32_t ao = (uint32_t)cur * A_STG_B;
        const uint32_t bo = (uint32_t)cur * B_STG_B;
#pragma unroll
        for (int ks = 0; ks < 4; ks++) {
            uint32_t af0[4], af1[4];
            ldsm4(af0, aAddr[0] + ao + ks * 32);
            ldsm4(af1, aAddr[1] + ao + ks * 32);
#pragma unroll
            for (int p = 0; p < 4; p++) {
                uint32_t bf[4];
                ldsm4(bf, bAddr[p] + bo + ks * 32);
                mma16(acc[0][2 * p],     af0, bf[0], bf[1]);
                mma16(acc[1][2 * p],     af1, bf[0], bf[1]);
                mma16(acc[0][2 * p + 1], af0, bf[2], bf[3]);
                mma16(acc[1][2 * p + 1], af1, bf[2], bf[3]);
            }
        }
        cur ^= 1;
    }

    // ---- LayerNorm reduction ----
    __syncthreads();
#pragma unroll
    for (int mt = 0; mt < 2; mt++) {
        float s1a = 0.f, s2a = 0.f, s1b = 0.f, s2b = 0.f;
#pragma unroll
        for (int nt = 0; nt < 8; nt++) {
            float v0 = acc[mt][nt][0], v1 = acc[mt][nt][1];
            float v2 = acc[mt][nt][2], v3 = acc[mt][nt][3];
            s1a += v0 + v1; s2a += v0 * v0 + v1 * v1;
            s1b += v2 + v3; s2b += v2 * v2 + v3 * v3;
        }
#pragma unroll
        for (int o = 1; o < 4; o <<= 1) {
            s1a += __shfl_xor_sync(0xFFFFFFFFu, s1a, o);
            s2a += __shfl_xor_sync(0xFFFFFFFFu, s2a, o);
            s1b += __shfl_xor_sync(0xFFFFFFFFu, s1b, o);
            s2b += __shfl_xor_sync(0xFFFFFFFFu, s2b, o);
        }
        if ((lane & 3) == 0) {
            int r = (wm << 5) + (mt << 4) + (lane >> 2);
            sm->red1[r][wn] = s1a; sm->red2[r][wn] = s2a;
            sm->red1[r + 8][wn] = s1b; sm->red2[r + 8][wn] = s2b;
        }
    }
    __syncthreads();
    if (tid < BM) {
        float s1 = sm->red1[tid][0] + sm->red1[tid][1] + sm->red1[tid][2] + sm->red1[tid][3];
        float s2 = sm->red2[tid][0] + sm->red2[tid][1] + sm->red2[tid][2] + sm->red2[tid][3];
        float mu  = s1 * (1.0f / 256.0f);
        float var = s2 * (1.0f / 256.0f) - mu * mu;
        sm->mu[tid]  = mu;
        sm->inv[tid] = rsqrtf(var + 1e-6f);
    }
    __syncthreads();

    // ---- normalize + residual + GELU + store ----
#pragma unroll
    for (int mt = 0; mt < 2; mt++) {
#pragma unroll
        for (int hf = 0; hf < 2; hf++) {
            int r = (wm << 5) + (mt << 4) + (lane >> 2) + hf * 8;
            int m = m0 + r;
            if (m < NPTS) {
                float mu = sm->mu[r], inv = sm->inv[r];
#pragma unroll
                for (int nt = 0; nt < 8; nt++) {
                    int n = (wn << 6) + nt * 8 + ((lane & 3) << 1);
                    float v0 = acc[mt][nt][hf * 2 + 0];
                    float v1 = acc[mt][nt][hf * 2 + 1];
                    v0 = (v0 - mu) * inv * sm->gam[n]     + sm->bet[n];
                    v1 = (v1 - mu) * inv * sm->gam[n + 1] + sm->bet[n + 1];
                    if (HAS_RES) {
                        float2 rr = *(const float2*)(resid + (size_t)m * CDIM + n);
                        v0 += rr.x; v1 += rr.y;
                    }
                    v0 = gelu_exact(v0);
                    v1 = gelu_exact(v1);
                    if (HALF_OUT) {
                        __half2 h = __floats2half2_rn(v0, v1);
                        *(__half2*)((__half*)dst_v + (size_t)m * CDIM + n) = h;
                    } else {
                        *(float2*)((float*)dst_v + (size_t)m * CDIM + n) = make_float2(v0, v1);
                    }
                }
            }
        }
    }
}

// ---------------- launch (3 kernels) ----------------
extern "C" void kernel_launch(void* const* d_in, const int* in_sizes, int n_in,
                              void* d_out, int out_size) {
    const float* feats  = (const float*)d_in[0];
    const float* W1     = (const float*)d_in[1];
    const float* gamma1 = (const float*)d_in[2];
    const float* beta1  = (const float*)d_in[3];
    const float* W2     = (const float*)d_in[4];
    const float* gamma2 = (const float*)d_in[5];
    const float* beta2  = (const float*)d_in[6];
    const int*   nbr    = (const int*)d_in[7];
    const void*  mask   = (const void*)d_in[8];

    __half *hfeats, *mid, *wt1, *wt2;
    cudaGetSymbolAddress((void**)&hfeats, g_hfeats);
    cudaGetSymbolAddress((void**)&mid, g_mid);
    cudaGetSymbolAddress((void**)&wt1, g_WT1);
    cudaGetSymbolAddress((void**)&wt2, g_WT2);

    const int smem_bytes = (int)sizeof(Smem);
    cudaFuncSetAttribute(conv_mma<false, true>, cudaFuncAttributeMaxDynamicSharedMemorySize, smem_bytes);
    cudaFuncSetAttribute(conv_mma<true, false>, cudaFuncAttributeMaxDynamicSharedMemorySize, smem_bytes);

    prepass_kernel<<<PRE_BLOCKS, THREADS>>>(feats, W1, W2, nbr, mask, hfeats, wt1, wt2);

    const int grid = (NPTS + BM - 1) / BM;  // 1563
    conv_mma<false, true><<<grid, THREADS, smem_bytes>>>(hfeats, wt1, gamma1, beta1, nullptr, mid);
    conv_mma<true, false><<<grid, THREADS, smem_bytes>>>(mid,  wt2, gamma2, beta2, feats, d_out);
}